// round 16
// baseline (speedup 1.0000x reference)
#include <cuda_runtime.h>

#define TT   2048
#define HB   128
#define NL   3
#define NGR  8     // gate-groups per layer (64 rows each)
#define NBG  4     // batch-groups per layer (32 cols each)
#define RPC  64    // gate rows per CTA
#define JPC  16    // hidden j per CTA

// KP: padded K per layer. L0: 16 (x pad 6->16) + 128 = 144 ; L1/2: 256.
#define KP0 144
#define KP12 256
#define WSZ0 (NGR*RPC*KP0)
#define WSZ12 (NGR*RPC*KP12)
#define WO0 0
#define WO1 WSZ0
#define WO2 (WSZ0 + WSZ12)

// h history, PAIR-PACKED: (l, slot, j, b) at ((l*(TT+1)+slot)*64 + (j>>1))*256 + b*2 + (j&1)
__device__ __align__(16) float g_H[(size_t)NL * (TT + 1) * HB * HB];
// x transposed, pair-packed, padded 6->16: (t, i, b) at t*2048 + (i>>1)*256 + b*2 + (i&1)
__device__ __align__(16) float g_xT[(size_t)TT * 2048];
__device__ float g_Wp[WSZ0 + 2 * WSZ12];
__device__ float g_bias[NL * NGR * RPC];
// flag[(l*4+bg)*32 + gr] = completed steps of CTA (l, gr, bg); 128B line per (l,bg)
__device__ __align__(128) int g_flags[NL * NBG * 32];

typedef unsigned long long ull;

__device__ __forceinline__ ull pk2(float lo, float hi) {
    ull r; asm("mov.b64 %0,{%1,%2};" : "=l"(r) : "f"(lo), "f"(hi)); return r;
}
__device__ __forceinline__ float sum2(ull v) {
    float lo, hi; asm("mov.b64 {%0,%1},%2;" : "=f"(lo), "=f"(hi) : "l"(v));
    return lo + hi;
}
__device__ __forceinline__ ull ffma2(ull a, ull b, ull c) {
    ull d; asm("fma.rn.f32x2 %0,%1,%2,%3;" : "=l"(d) : "l"(a), "l"(b), "l"(c));
    return d;
}
__device__ __forceinline__ int ldacq(const int* p) {
    int v; asm volatile("ld.acquire.gpu.global.b32 %0,[%1];" : "=r"(v) : "l"(p) : "memory");
    return v;
}
__device__ __forceinline__ void strel(int* p, int v) {
    asm volatile("st.release.gpu.global.b32 [%0],%1;" :: "l"(p), "r"(v) : "memory");
}
__device__ __forceinline__ float sigf(float x) {
    return __fdividef(1.0f, 1.0f + __expf(-x));
}
__device__ __forceinline__ float tanhf_fast(float x) {
    return __fdividef(2.0f, 1.0f + __expf(-2.0f * x)) - 1.0f;
}

// ============ setup ============
// blocks [0,24): pack (l=blk/8, gr=blk%8); [24,24+TT): xT; last 3: zero H slot 0.
__global__ void setup_kernel(
    const float* __restrict__ x,
    const float* __restrict__ Wih0, const float* __restrict__ Whh0,
    const float* __restrict__ bih0, const float* __restrict__ bhh0,
    const float* __restrict__ Wih1, const float* __restrict__ Whh1,
    const float* __restrict__ bih1, const float* __restrict__ bhh1,
    const float* __restrict__ Wih2, const float* __restrict__ Whh2,
    const float* __restrict__ bih2, const float* __restrict__ bhh2)
{
    int blk = blockIdx.x, tid = threadIdx.x;
    if (blk < NL * NGR) {
        int l = blk / NGR, gr = blk % NGR;
        const float* Wih = (l == 0) ? Wih0 : ((l == 1) ? Wih1 : Wih2);
        const float* Whh = (l == 0) ? Whh0 : ((l == 1) ? Whh1 : Whh2);
        const float* bih = (l == 0) ? bih0 : ((l == 1) ? bih1 : bih2);
        const float* bhh = (l == 0) ? bhh0 : ((l == 1) ? bhh1 : bhh2);
        int XC = (l == 0) ? 16 : 128;
        int KP = XC + 128;
        int base = ((l == 0) ? WO0 : ((l == 1) ? WO1 : WO2)) + gr * RPC * KP;
        for (int idx = tid; idx < RPC * KP; idx += blockDim.x) {
            int r = idx / KP, k = idx % KP;
            int R = (r >> 4) * 128 + gr * JPC + (r & 15);
            float v;
            if (k < XC) v = (l == 0) ? ((k < 6) ? Wih[R * 6 + k] : 0.0f)
                                     : Wih[R * 128 + k];
            else        v = Whh[R * 128 + (k - XC)];
            g_Wp[base + idx] = v;
        }
        if (tid < RPC) {
            int R = (tid >> 4) * 128 + gr * JPC + (tid & 15);
            g_bias[(l * NGR + gr) * RPC + tid] = bih[R] + bhh[R];
        }
        if (blk == 0 && tid < NL * NBG * 32) g_flags[tid] = 0;
    } else if (blk < NL * NGR + TT) {
        int t = blk - NL * NGR;
        if (tid < HB) {
            #pragma unroll
            for (int i = 0; i < 16; i++) {
                float v = (i < 6) ? x[(size_t)tid * (TT * 6) + t * 6 + i] : 0.0f;
                g_xT[(size_t)t * 2048 + (i >> 1) * 256 + tid * 2 + (i & 1)] = v;
            }
        }
    } else {
        size_t base = (size_t)(blk - NL * NGR - TT) * (TT + 1) * HB * HB;
        for (int i = tid; i < HB * HB; i += blockDim.x) g_H[base + i] = 0.0f;
    }
}

// ---- GEMM part: NG groups of 4 cols, 16 rows, 1 batch col (lane baked into p).
// p = pair-packed src + lane's batch f2 index; wb = Wsm row-base + weight col.
template<int KP, int NG>
__device__ __forceinline__ void gemm_part(const float2* __restrict__ p,
                                          const float* __restrict__ wb,
                                          ull* acc /*16*/)
{
    #pragma unroll
    for (int i = 0; i < NG; i++) {
        float2 a01 = __ldcg(p + (2 * i) * 128);
        float2 a23 = __ldcg(p + (2 * i + 1) * 128);
        ull h01 = pk2(a01.x, a01.y), h23 = pk2(a23.x, a23.y);
        const float* w0 = wb + 4 * i;
        #pragma unroll
        for (int r = 0; r < 16; r++) {
            ulonglong2 w = *(const ulonglong2*)(w0 + r * KP);  // LDS.128 bcast
            acc[r] = ffma2(w.x, h01, acc[r]);
            acc[r] = ffma2(w.y, h23, acc[r]);
        }
    }
}

// ---- per-CTA persistent body. CTA = (L, gr, bg): 64 gate rows x 32 batch cols.
// 512 thr = 16 warps: rg = warp&3 (16-row group), kq = warp>>2 (K quarter, 64 cols);
// lane = batch col within the CTA's 32. Epilogue: thread (j = tid>>5, b = tid&31).
template<int L>
__device__ __forceinline__ void lstm_run(int gr, int bg,
                                         float* Wsm, float* RD, float* bsm)
{
    constexpr int XC = (L == 0) ? 16 : 128;
    constexpr int KP = XC + 128;
    constexpr int WO = (L == 0) ? WO0 : ((L == 1) ? WO1 : WO2);

    const int tid  = threadIdx.x;
    const int lane = tid & 31;
    const int warp = tid >> 5;
    const int rg   = warp & 3;
    const int kq   = warp >> 2;
    const int lb   = bg * 32 + lane;       // global batch f2 index
    const int j    = tid >> 5;             // epilogue: hidden j (0..15)
    const int b    = tid & 31;             // epilogue: batch within group

    for (int i = tid; i < RPC * KP; i += 512)
        Wsm[i] = g_Wp[WO + gr * RPC * KP + i];
    if (tid < RPC) bsm[tid] = g_bias[(L * NGR + gr) * RPC + tid];
    __syncthreads();

    int* ownf = g_flags + (L * NBG + bg) * 32;
    const int* belf = (L > 0) ? (g_flags + ((L - 1) * NBG + bg) * 32) : ownf;

    float c = 0.0f;

    for (int t = 0; t < TT; t++) {
        // ---- warp-0 dual-range spin: own layer >= t, below layer >= t+1
        if (warp == 0) {
            for (;;) {
                int bad = 0;
                if (lane < NGR) bad = (ldacq(ownf + lane) < t);
                else if (L > 0 && lane < 2 * NGR)
                    bad = (ldacq(belf + lane - NGR) < t + 1);
                if (__ballot_sync(0xffffffffu, bad) == 0u) break;
            }
        }
        __syncthreads();

        const float2* srcOwn = (const float2*)(g_H + (size_t)(L * (TT + 1) + t) * HB * HB);
        const float2* srcBel = (L == 0)
            ? (const float2*)(g_xT + (size_t)t * 2048)
            : (const float2*)(g_H + (size_t)((L - 1) * (TT + 1) + t + 1) * HB * HB);

        ull acc[16];
        #pragma unroll
        for (int r = 0; r < 16; r++) acc[r] = 0ULL;

        const float* Wr = Wsm + rg * 16 * KP;   // this warp's 16 rows

        if constexpr (L == 0) {
            // 144 cols / 4 kq = 36 each. kq0: x 0..15 + h 0..19; kq1-3: 36 h cols.
            if (kq == 0) {
                gemm_part<KP, 4>(srcBel + lb, Wr, acc);
                gemm_part<KP, 5>(srcOwn + lb, Wr + 16, acc);
            } else {
                gemm_part<KP, 9>(srcOwn + ((kq * 36 - 16) >> 1) * 128 + lb,
                                 Wr + kq * 36, acc);
            }
        } else {
            // 256 cols / 4 kq = 64 each (NG=16). kq0,1: ih; kq2,3: hh.
            if (kq < 2)
                gemm_part<KP, 16>(srcBel + (kq * 32) * 128 + lb, Wr + kq * 64, acc);
            else
                gemm_part<KP, 16>(srcOwn + ((kq - 2) * 32) * 128 + lb, Wr + kq * 64, acc);
        }

        #pragma unroll
        for (int r = 0; r < 16; r++)
            RD[(kq * RPC + rg * 16 + r) * 32 + lane] = sum2(acc[r]);
        __syncthreads();

        // ---- epilogue: thread (j, b); gate q's row = q*16 + j
        {
            float v0 = bsm[0 * 16 + j], v1 = bsm[1 * 16 + j];
            float v2 = bsm[2 * 16 + j], v3 = bsm[3 * 16 + j];
            #pragma unroll
            for (int k2 = 0; k2 < 4; k2++) {
                v0 += RD[(k2 * RPC + 0 * 16 + j) * 32 + b];
                v1 += RD[(k2 * RPC + 1 * 16 + j) * 32 + b];
                v2 += RD[(k2 * RPC + 2 * 16 + j) * 32 + b];
                v3 += RD[(k2 * RPC + 3 * 16 + j) * 32 + b];
            }
            float iv = sigf(v0);
            float fv = sigf(v1);
            float gv = tanhf_fast(v2);
            float ov = sigf(v3);
            c = fv * c + iv * gv;
            int jg = gr * JPC + j;
            float* Hout = g_H + (size_t)(L * (TT + 1) + t + 1) * HB * HB;
            __stcg(Hout + (jg >> 1) * 256 + (bg * 32 + b) * 2 + (jg & 1),
                   ov * tanhf_fast(c));
        }
        __syncthreads();   // h stores program-ordered before the release
        if (tid == 0) strel(ownf + gr, t + 1);
    }
}

__global__ void __launch_bounds__(512, 1) lstm_kernel(
    const float* __restrict__ W_out, const float* __restrict__ b_out,
    float* __restrict__ out)
{
    extern __shared__ float sm[];
    float* Wsm = sm;                         // up to 64*256 floats (64 KB)
    float* RD  = sm + RPC * KP12;            // 4*64*32 floats (32 KB)
    float* bsm = RD + 4 * RPC * 32;          // 64 floats

    const int blk = blockIdx.x;
    const int l = blk >> 5, rem = blk & 31;
    const int gr = rem & 7, bg = rem >> 3;
    if (l == 0)      lstm_run<0>(gr, bg, Wsm, RD, bsm);
    else if (l == 1) lstm_run<1>(gr, bg, Wsm, RD, bsm);
    else             lstm_run<2>(gr, bg, Wsm, RD, bsm);

    // ---- head folded into CTA 64 (l=2, gr=0, bg=0)
    if (blk == 2 * 32) {
        if (threadIdx.x < 32) {
            int lane = threadIdx.x;
            const int* fl = g_flags + (2 * NBG + (lane >> 3)) * 32 + (lane & 7);
            int f = ldacq(fl);
            while (__ballot_sync(0xffffffffu, f < TT)) f = ldacq(fl);
        }
        __syncthreads();
        if (threadIdx.x < HB) {
            const float* h = g_H + (size_t)(2 * (TT + 1) + TT) * HB * HB;
            int bb = threadIdx.x;
            float s = b_out[0];
            #pragma unroll 8
            for (int jj = 0; jj < HB; jj++)
                s += __ldcg(h + (jj >> 1) * 256 + bb * 2 + (jj & 1)) * W_out[jj];
            out[bb] = s;
        }
    }
}

extern "C" void kernel_launch(void* const* d_in, const int* in_sizes, int n_in,
                              void* d_out, int out_size)
{
    (void)in_sizes; (void)n_in; (void)out_size;

    const int SMEM_DYN = (RPC * KP12 + 4 * RPC * 32 + RPC) * 4;   // 98,560 B
    cudaFuncSetAttribute(lstm_kernel,
                         cudaFuncAttributeMaxDynamicSharedMemorySize, SMEM_DYN);

    setup_kernel<<<NL * NGR + TT + NL, 512>>>(
        (const float*)d_in[0],
        (const float*)d_in[1], (const float*)d_in[2],
        (const float*)d_in[3], (const float*)d_in[4],
        (const float*)d_in[5], (const float*)d_in[6],
        (const float*)d_in[7], (const float*)d_in[8],
        (const float*)d_in[9], (const float*)d_in[10],
        (const float*)d_in[11], (const float*)d_in[12]);
    lstm_kernel<<<NL * NGR * NBG, 512, SMEM_DYN>>>(
        (const float*)d_in[13], (const float*)d_in[14], (float*)d_out);
}